// round 2
// baseline (speedup 1.0000x reference)
#include <cuda_runtime.h>
#include <cstdint>

// Fixed shapes: x,y float32 (4,4096,6)
#define BB 4
#define NN 4096
#define NPTS (BB*NN)
#define LOG2E 1.4426950408889634f
#define LN2F  0.6931471805599453f
#define EPS2  1e-4f
#define BLOG  (-8.317766166719343f)   // -log(4096)
#define POS_INF (__int_as_float(0x7f800000))
#define NEG_INF (__int_as_float(0xff800000))

#define PBUF (8*NN*16)                // floats per P buffer (8 segs x 4096 j x 16 floats)

// ---- f32x2 packed-math helpers (sm_103a) ----
#define FMA2(d,a,b,c) asm("fma.rn.f32x2 %0, %1, %2, %3;" : "=l"(d) : "l"(a), "l"(b), "l"(c))
#define ADD2(d,a,b)   asm("add.rn.f32x2 %0, %1, %2;"     : "=l"(d) : "l"(a), "l"(b))
#define MUL2(d,a,b)   asm("mul.rn.f32x2 %0, %1, %2;"     : "=l"(d) : "l"(a), "l"(b))
__device__ __forceinline__ unsigned long long pack2(float lo, float hi) {
    unsigned long long d;
    asm("mov.b64 %0, {%1, %2};" : "=l"(d) : "r"(__float_as_uint(lo)), "r"(__float_as_uint(hi)));
    return d;
}
__device__ __forceinline__ void unpack2(float& lo, float& hi, unsigned long long d) {
    unsigned int a, b;
    asm("mov.b64 {%0, %1}, %2;" : "=r"(a), "=r"(b) : "l"(d));
    lo = __uint_as_float(a); hi = __uint_as_float(b);
}
__device__ __forceinline__ float ex2(float x) {   // raw MUFU.EX2
    float r; asm("ex2.approx.ftz.f32 %0, %1;" : "=f"(r) : "f"(x)); return r;
}

// -------- device scratch --------
__device__ __align__(16) float d_U[NPTS*8];       // scaled x points: u0..u5, |u|^2, pad
__device__ __align__(16) float d_V[NPTS*8];       // scaled y points
__device__ __align__(16) float d_Pbuf[2*PBUF];    // ping-pong packed column data
__device__ float d_f[2][NPTS];
__device__ float d_g[2][NPTS];
__device__ float d_maxnorm2;
__device__ float d_dmin[6];
__device__ float d_dmax[6];
__device__ float d_eps1;

__device__ __forceinline__ void atomicMaxF(float* addr, float v) {
    if (v >= 0.f) atomicMax((int*)addr, __float_as_int(v));
    else          atomicMin((unsigned int*)addr, __float_as_uint(v));
}
__device__ __forceinline__ void atomicMinF(float* addr, float v) {
    if (v >= 0.f) atomicMin((int*)addr, __float_as_int(v));
    else          atomicMax((unsigned int*)addr, __float_as_uint(v));
}

// -------- kernel 0: reset reduction scalars --------
__global__ void k_init() {
    if (threadIdx.x == 0) {
        d_maxnorm2 = 0.f;
        #pragma unroll
        for (int k = 0; k < 6; ++k) { d_dmin[k] = POS_INF; d_dmax[k] = NEG_INF; }
    }
}

// -------- kernel 1: max coord-norm + per-dim min/max --------
__global__ void k_reduce(const float* __restrict__ x, const float* __restrict__ y) {
    int idx = blockIdx.x * blockDim.x + threadIdx.x;
    int stride = gridDim.x * blockDim.x;
    float mn2 = 0.f;
    float dmn[6], dmx[6];
    #pragma unroll
    for (int k = 0; k < 6; ++k) { dmn[k] = POS_INF; dmx[k] = NEG_INF; }
    for (int p = idx; p < 2*NPTS; p += stride) {
        const float* v = (p < NPTS) ? (x + (size_t)p*6) : (y + (size_t)(p - NPTS)*6);
        float c[6];
        #pragma unroll
        for (int k = 0; k < 6; ++k) c[k] = v[k];
        float n2 = c[0]*c[0] + c[1]*c[1] + c[2]*c[2];
        mn2 = fmaxf(mn2, n2);
        #pragma unroll
        for (int k = 0; k < 6; ++k) { dmn[k] = fminf(dmn[k], c[k]); dmx[k] = fmaxf(dmx[k], c[k]); }
    }
    #pragma unroll
    for (int o = 16; o; o >>= 1) {
        mn2 = fmaxf(mn2, __shfl_xor_sync(0xffffffffu, mn2, o));
        #pragma unroll
        for (int k = 0; k < 6; ++k) {
            dmn[k] = fminf(dmn[k], __shfl_xor_sync(0xffffffffu, dmn[k], o));
            dmx[k] = fmaxf(dmx[k], __shfl_xor_sync(0xffffffffu, dmx[k], o));
        }
    }
    __shared__ float s2[8], smn[8][6], smx[8][6];
    int lane = threadIdx.x & 31, w = threadIdx.x >> 5;
    if (lane == 0) {
        s2[w] = mn2;
        #pragma unroll
        for (int k = 0; k < 6; ++k) { smn[w][k] = dmn[k]; smx[w][k] = dmx[k]; }
    }
    __syncthreads();
    if (threadIdx.x == 0) {
        float a2 = s2[0];
        float amn[6], amx[6];
        #pragma unroll
        for (int k = 0; k < 6; ++k) { amn[k] = smn[0][k]; amx[k] = smx[0][k]; }
        for (int wi = 1; wi < 8; ++wi) {
            a2 = fmaxf(a2, s2[wi]);
            #pragma unroll
            for (int k = 0; k < 6; ++k) {
                amn[k] = fminf(amn[k], smn[wi][k]);
                amx[k] = fmaxf(amx[k], smx[wi][k]);
            }
        }
        atomicMaxF(&d_maxnorm2, a2);
        #pragma unroll
        for (int k = 0; k < 6; ++k) { atomicMinF(&d_dmin[k], amn[k]); atomicMaxF(&d_dmax[k], amx[k]); }
    }
}

// -------- pack helper: write one column j (duplicated pairs, 64B) --------
__device__ __forceinline__ void write_pack(float* dst, float w0, float w1, float w2,
                                           float w3, float w4, float w5, float h2) {
    reinterpret_cast<float4*>(dst)[0] = make_float4(w0, w0, w1, w1);
    reinterpret_cast<float4*>(dst)[1] = make_float4(w2, w2, w3, w3);
    reinterpret_cast<float4*>(dst)[2] = make_float4(w4, w4, w5, w5);
    reinterpret_cast<float4*>(dst)[3] = make_float4(h2, h2, 0.f, 0.f);
}

// -------- kernel 2: build U/V + initial pack (pot=0, eps1, natural-log units) --------
__global__ void k_build(const float* __restrict__ x, const float* __restrict__ y) {
    int p = blockIdx.x * blockDim.x + threadIdx.x;
    if (p >= 2*NPTS) return;
    float s = 1.f / (sqrtf(d_maxnorm2) + 1e-6f);
    float e = 0.f;
    #pragma unroll
    for (int k = 0; k < 6; ++k) { float d = d_dmax[k] - d_dmin[k]; e += d * d; }
    float inv_eps1 = 1.f / e;

    int q = (p < NPTS) ? p : p - NPTS;
    const float* src = (p < NPTS) ? (x + (size_t)q*6) : (y + (size_t)q*6);
    float* dst = (p < NPTS) ? (d_U + (size_t)q*8) : (d_V + (size_t)q*8);
    float u0 = src[0]*s, u1 = src[1]*s, u2 = src[2]*s;
    float c3 = 0.1f * fminf(fmaxf(src[3], 0.f), 1.f);
    float c4 = 0.1f * fminf(fmaxf(src[4], 0.f), 1.f);
    float c5 = 0.1f * fminf(fmaxf(src[5], 0.f), 1.f);
    float sq = u0*u0 + u1*u1 + u2*u2 + c3*c3 + c4*c4 + c5*c5;
    reinterpret_cast<float4*>(dst)[0] = make_float4(u0, u1, u2, c3);
    reinterpret_cast<float4*>(dst)[1] = make_float4(c4, c5, sq, 0.f);

    // x points are columns for dir=1 (g-softmin), y points for dir=0 (f-softmin)
    int seg = ((p < NPTS) ? 1 : 0) * 4 + (q >> 12);
    int j = q & (NN - 1);
    float cw = 2.f * inv_eps1;
    float h2 = (0.f - sq) * inv_eps1;   // pot = 0
    write_pack(d_Pbuf + ((size_t)seg*NN + j)*16, u0*cw, u1*cw, u2*cw, c3*cw, c4*cw, c5*cw, h2);
}

// -------- main fused softmin (both directions), 128 rows/block, 8-warp j-split --------
// EPS1S: use 4th-order Taylor sum (args tiny), else streaming-max logsumexp.
// HASNEXT: epilogue also packs next-stage column data into the other P buffer.
template<bool EPS1S, bool NEXT1, bool HASNEXT>
__global__ void __launch_bounds__(256) k_main(int cur, int pp, float alpha, float beta) {
    const int bd = blockIdx.y;
    const int b = bd & 3;
    const int dir = bd >> 2;
    const float* Rows = (dir ? d_V : d_U) + (size_t)b*NN*8;
    const float* fin  = (dir ? d_g[cur] : d_f[cur]) + (size_t)b*NN;
    float* fout       = (dir ? d_g[cur^1] : d_f[cur^1]) + (size_t)b*NN;
    const float* Pin  = d_Pbuf + (size_t)pp*PBUF + (size_t)(dir*4 + b)*NN*16;

    const int lane = threadIdx.x & 31;
    const int warp = threadIdx.x >> 5;
    const int rowbase = blockIdx.x * 128;

    // pack u for 4 rows into f32x2 pairs: pair0 = rows (lane, lane+32), pair1 = (+64, +96)
    unsigned long long up[2][6];
    #pragma unroll
    for (int pr = 0; pr < 2; ++pr) {
        const float4* ra = reinterpret_cast<const float4*>(Rows + (size_t)(rowbase + lane + 64*pr)*8);
        const float4* rb = reinterpret_cast<const float4*>(Rows + (size_t)(rowbase + lane + 64*pr + 32)*8);
        float4 a0 = ra[0], a1 = ra[1];
        float4 b0 = rb[0], b1 = rb[1];
        up[pr][0] = pack2(a0.x, b0.x); up[pr][1] = pack2(a0.y, b0.y);
        up[pr][2] = pack2(a0.z, b0.z); up[pr][3] = pack2(a0.w, b0.w);
        up[pr][4] = pack2(a1.x, b1.x); up[pr][5] = pack2(a1.y, b1.y);
    }

    const unsigned long long* P8 = reinterpret_cast<const unsigned long long*>(Pin) + (size_t)warp*512*8;

    // accumulators
    unsigned long long T1[2] = {0,0}, T2[2] = {0,0}, T3[2] = {0,0}, T4[2] = {0,0};
    float m0 = NEG_INF, m1 = NEG_INF, m2 = NEG_INF, m3 = NEG_INF;
    float s0 = 0.f, s1 = 0.f, s2 = 0.f, s3 = 0.f;

    #pragma unroll 4
    for (int j = 0; j < 512; ++j) {
        ulonglong2 q0 = *reinterpret_cast<const ulonglong2*>(P8 + 8*j + 0);
        ulonglong2 q1 = *reinterpret_cast<const ulonglong2*>(P8 + 8*j + 2);
        ulonglong2 q2 = *reinterpret_cast<const ulonglong2*>(P8 + 8*j + 4);
        unsigned long long hp = P8[8*j + 6];
        unsigned long long A0 = hp, A1 = hp;
        FMA2(A0, up[0][0], q0.x, A0);  FMA2(A1, up[1][0], q0.x, A1);
        FMA2(A0, up[0][1], q0.y, A0);  FMA2(A1, up[1][1], q0.y, A1);
        FMA2(A0, up[0][2], q1.x, A0);  FMA2(A1, up[1][2], q1.x, A1);
        FMA2(A0, up[0][3], q1.y, A0);  FMA2(A1, up[1][3], q1.y, A1);
        FMA2(A0, up[0][4], q2.x, A0);  FMA2(A1, up[1][4], q2.x, A1);
        FMA2(A0, up[0][5], q2.y, A0);  FMA2(A1, up[1][5], q2.y, A1);
        if (EPS1S) {
            unsigned long long X0, X1;
            MUL2(X0, A0, A0);             MUL2(X1, A1, A1);
            ADD2(T1[0], T1[0], A0);       ADD2(T1[1], T1[1], A1);
            ADD2(T2[0], T2[0], X0);       ADD2(T2[1], T2[1], X1);
            FMA2(T3[0], X0, A0, T3[0]);   FMA2(T3[1], X1, A1, T3[1]);
            FMA2(T4[0], X0, X0, T4[0]);   FMA2(T4[1], X1, X1, T4[1]);
        } else {
            float a0, a1, a2, a3;
            unpack2(a0, a1, A0); unpack2(a2, a3, A1);
            { float d = a0 - m0; float ee = ex2(-fabsf(d)); bool up_ = d > 0.f;
              s0 = up_ ? fmaf(s0, ee, 1.f) : (s0 + ee); m0 = fmaxf(m0, a0); }
            { float d = a1 - m1; float ee = ex2(-fabsf(d)); bool up_ = d > 0.f;
              s1 = up_ ? fmaf(s1, ee, 1.f) : (s1 + ee); m1 = fmaxf(m1, a1); }
            { float d = a2 - m2; float ee = ex2(-fabsf(d)); bool up_ = d > 0.f;
              s2 = up_ ? fmaf(s2, ee, 1.f) : (s2 + ee); m2 = fmaxf(m2, a2); }
            { float d = a3 - m3; float ee = ex2(-fabsf(d)); bool up_ = d > 0.f;
              s3 = up_ ? fmaf(s3, ee, 1.f) : (s3 + ee); m3 = fmaxf(m3, a3); }
        }
    }

    __shared__ float shA[8][128];
    __shared__ float shB[8][128];
    if (EPS1S) {
        // per-warp partial S contribution per row (4th-order Taylor of sum e^x)
        float t1a, t1b, t1c, t1d, t2a, t2b, t2c, t2d;
        float t3a, t3b, t3c, t3d, t4a, t4b, t4c, t4d;
        unpack2(t1a, t1b, T1[0]); unpack2(t1c, t1d, T1[1]);
        unpack2(t2a, t2b, T2[0]); unpack2(t2c, t2d, T2[1]);
        unpack2(t3a, t3b, T3[0]); unpack2(t3c, t3d, T3[1]);
        unpack2(t4a, t4b, T4[0]); unpack2(t4c, t4d, T4[1]);
        shA[warp][lane      ] = 512.f + t1a + 0.5f*t2a + (1.f/6.f)*t3a + (1.f/24.f)*t4a;
        shA[warp][lane + 32 ] = 512.f + t1b + 0.5f*t2b + (1.f/6.f)*t3b + (1.f/24.f)*t4b;
        shA[warp][lane + 64 ] = 512.f + t1c + 0.5f*t2c + (1.f/6.f)*t3c + (1.f/24.f)*t4c;
        shA[warp][lane + 96 ] = 512.f + t1d + 0.5f*t2d + (1.f/6.f)*t3d + (1.f/24.f)*t4d;
    } else {
        shA[warp][lane      ] = m0;  shB[warp][lane      ] = s0;
        shA[warp][lane + 32 ] = m1;  shB[warp][lane + 32 ] = s1;
        shA[warp][lane + 64 ] = m2;  shB[warp][lane + 64 ] = s2;
        shA[warp][lane + 96 ] = m3;  shB[warp][lane + 96 ] = s3;
    }
    __syncthreads();

    if (threadIdx.x < 128) {
        const int t = threadIdx.x;
        const int r = rowbase + t;
        float eps1 = d_eps1;
        float val;
        if (EPS1S) {
            float S = 0.f;
            #pragma unroll
            for (int w = 0; w < 8; ++w) S += shA[w][t];
            val = Rows[(size_t)r*8 + 6] - eps1 * (BLOG + logf(S));
        } else {
            float M = shA[0][t];
            #pragma unroll
            for (int w = 1; w < 8; ++w) M = fmaxf(M, shA[w][t]);
            float S = 0.f;
            #pragma unroll
            for (int w = 0; w < 8; ++w) S += shB[w][t] * exp2f(shA[w][t] - M);
            val = Rows[(size_t)r*8 + 6] - EPS2 * LN2F * (M + log2f(S));
        }
        float res = beta * val;
        if (alpha != 0.f) res = fmaf(alpha, fin[r], res);
        fout[r] = res;

        if (HASNEXT) {
            // pack this row as a COLUMN for the opposite direction of the next stage
            const float* src = Rows + (size_t)r*8;
            float c0 = src[0], c1 = src[1], c2 = src[2];
            float c3 = src[3], c4 = src[4], c5 = src[5], sq = src[6];
            float cw, h2;
            if (NEXT1) {
                float ie = 1.f / eps1;
                cw = 2.f * ie;
                h2 = (res - sq) * ie;
            } else {
                cw = 2.f * LOG2E / EPS2;
                h2 = LOG2E * BLOG + (res - sq) * (LOG2E / EPS2);
            }
            float* dst = d_Pbuf + (size_t)(pp^1)*PBUF + ((size_t)((dir^1)*4 + b)*NN + r)*16;
            write_pack(dst, c0*cw, c1*cw, c2*cw, c3*cw, c4*cw, c5*cw, h2);
        }
    }
}

// -------- kernel: eps1 = diameter^2 scalar (1 thread) --------
__global__ void k_eps() {
    float e = 0.f;
    #pragma unroll
    for (int k = 0; k < 6; ++k) { float d = d_dmax[k] - d_dmin[k]; e += d * d; }
    d_eps1 = e;
}

// -------- final mean reduction --------
__global__ void k_out(float* __restrict__ out) {
    float sum = 0.f;
    for (int i = threadIdx.x; i < NPTS; i += 256)
        sum += d_f[0][i] + d_g[0][i];
    #pragma unroll
    for (int o = 16; o; o >>= 1) sum += __shfl_xor_sync(0xffffffffu, sum, o);
    __shared__ float sw[8];
    int lane = threadIdx.x & 31, w = threadIdx.x >> 5;
    if (lane == 0) sw[w] = sum;
    __syncthreads();
    if (threadIdx.x == 0) {
        float t = 0.f;
        #pragma unroll
        for (int wi = 0; wi < 8; ++wi) t += sw[wi];
        out[0] = t * (10.f / (float)NPTS);
    }
}

extern "C" void kernel_launch(void* const* d_in, const int* in_sizes, int n_in,
                              void* d_out, int out_size) {
    (void)in_sizes; (void)n_in; (void)out_size;
    const float* x = (const float*)d_in[0];
    const float* y = (const float*)d_in[1];
    float* out = (float*)d_out;

    k_init<<<1, 32>>>();
    k_reduce<<<64, 256>>>(x, y);
    k_eps<<<1, 1>>>();
    k_build<<<(2*NPTS + 255)/256, 256>>>(x, y);

    dim3 g(NN/128, 2*BB);
    // stage 0 (eps1): f = softmin(eps1, Cxy, b_log), g = softmin(eps1, Cyx, a_log); pack next (eps1)
    k_main<true,  true,  true ><<<g, 256>>>(0, 0, 0.0f, 1.0f);
    // stage 1 (eps1): f,g = 0.5*(f + ft); pack next (eps2)
    k_main<true,  false, true ><<<g, 256>>>(1, 1, 0.5f, 0.5f);
    // stage 2 (eps2): f,g = 0.5*(f + ft); pack next (eps2)
    k_main<false, false, true ><<<g, 256>>>(0, 0, 0.5f, 0.5f);
    // stage 3 (eps2): f_new, g_new
    k_main<false, false, false><<<g, 256>>>(1, 1, 0.0f, 1.0f);

    k_out<<<1, 256>>>(out);
}

// round 3
// speedup vs baseline: 2.1093x; 2.1093x over previous
#include <cuda_runtime.h>
#include <cstdint>

// Fixed shapes: x,y float32 (4,4096,6)
#define BB 4
#define NN 4096
#define NPTS (BB*NN)
#define LOG2E 1.4426950408889634f
#define LN2F  0.6931471805599453f
#define EPS2  1e-4f
#define BLOG  (-8.317766166719343f)   // -log(4096)
#define EBLOG (2.44140625e-4f)        // exp(BLOG) = 1/4096
#define POS_INF (__int_as_float(0x7f800000))
#define NEG_INF (__int_as_float(0xff800000))

#define PBUF (8*NN*16)                // floats per P buffer

// ---- f32x2 packed-math helpers ----
#define FMA2(d,a,b,c) asm("fma.rn.f32x2 %0, %1, %2, %3;" : "=l"(d) : "l"(a), "l"(b), "l"(c))
__device__ __forceinline__ unsigned long long pack2(float lo, float hi) {
    unsigned long long d;
    asm("mov.b64 %0, {%1, %2};" : "=l"(d) : "r"(__float_as_uint(lo)), "r"(__float_as_uint(hi)));
    return d;
}
__device__ __forceinline__ void unpack2(float& lo, float& hi, unsigned long long d) {
    unsigned int a, b;
    asm("mov.b64 {%0, %1}, %2;" : "=r"(a), "=r"(b) : "l"(d));
    lo = __uint_as_float(a); hi = __uint_as_float(b);
}
__device__ __forceinline__ float ex2(float x) {
    float r; asm("ex2.approx.ftz.f32 %0, %1;" : "=f"(r) : "f"(x)); return r;
}

// -------- device scratch --------
__device__ __align__(16) float d_U[NPTS*8];       // scaled x points: u0..u5, |u|^2, pad
__device__ __align__(16) float d_V[NPTS*8];       // scaled y points
__device__ __align__(16) float d_Pbuf[2*PBUF];    // packed eps2 column data (ping/pong)
__device__ float d_f[2][NPTS];
__device__ float d_g[2][NPTS];
__device__ float d_M0[8*32];                      // stage-0 moments: 28 per segment
__device__ float d_M1[8*32];                      // stage-1 moments
__device__ float d_maxnorm2;
__device__ float d_dmin[6];
__device__ float d_dmax[6];

__device__ __forceinline__ void atomicMaxF(float* addr, float v) {
    if (v >= 0.f) atomicMax((int*)addr, __float_as_int(v));
    else          atomicMin((unsigned int*)addr, __float_as_uint(v));
}
__device__ __forceinline__ void atomicMinF(float* addr, float v) {
    if (v >= 0.f) atomicMin((int*)addr, __float_as_int(v));
    else          atomicMax((unsigned int*)addr, __float_as_uint(v));
}

__device__ __forceinline__ float diameter2() {
    float e = 0.f;
    #pragma unroll
    for (int k = 0; k < 6; ++k) { float d = d_dmax[k] - d_dmin[k]; e += d * d; }
    return e;
}

// warp-reduce 28 accumulators, then one atomicAdd per lane
__device__ __forceinline__ void reduce28_atomic(const float* acc, float* gdst) {
    int lane = threadIdx.x & 31;
    float mine = 0.f;
    #pragma unroll
    for (int c = 0; c < 28; ++c) {
        float v = acc[c];
        #pragma unroll
        for (int o = 16; o; o >>= 1) v += __shfl_xor_sync(0xffffffffu, v, o);
        if (lane == c) mine = v;
    }
    if (lane < 28) atomicAdd(gdst + lane, mine);
}

// -------- kernel 0: reset scalars + zero moments --------
__global__ void k_init() {
    int t = threadIdx.x;
    if (t < 256) { if (t < 8*32) { d_M0[t] = 0.f; d_M1[t] = 0.f; } }
    if (t == 0) {
        d_maxnorm2 = 0.f;
        #pragma unroll
        for (int k = 0; k < 6; ++k) { d_dmin[k] = POS_INF; d_dmax[k] = NEG_INF; }
    }
}

// -------- kernel 1: max coord-norm + per-dim min/max --------
__global__ void k_reduce(const float* __restrict__ x, const float* __restrict__ y) {
    int idx = blockIdx.x * blockDim.x + threadIdx.x;
    int stride = gridDim.x * blockDim.x;
    float mn2 = 0.f;
    float dmn[6], dmx[6];
    #pragma unroll
    for (int k = 0; k < 6; ++k) { dmn[k] = POS_INF; dmx[k] = NEG_INF; }
    for (int p = idx; p < 2*NPTS; p += stride) {
        const float* v = (p < NPTS) ? (x + (size_t)p*6) : (y + (size_t)(p - NPTS)*6);
        float c[6];
        #pragma unroll
        for (int k = 0; k < 6; ++k) c[k] = v[k];
        float n2 = c[0]*c[0] + c[1]*c[1] + c[2]*c[2];
        mn2 = fmaxf(mn2, n2);
        #pragma unroll
        for (int k = 0; k < 6; ++k) { dmn[k] = fminf(dmn[k], c[k]); dmx[k] = fmaxf(dmx[k], c[k]); }
    }
    #pragma unroll
    for (int o = 16; o; o >>= 1) {
        mn2 = fmaxf(mn2, __shfl_xor_sync(0xffffffffu, mn2, o));
        #pragma unroll
        for (int k = 0; k < 6; ++k) {
            dmn[k] = fminf(dmn[k], __shfl_xor_sync(0xffffffffu, dmn[k], o));
            dmx[k] = fmaxf(dmx[k], __shfl_xor_sync(0xffffffffu, dmx[k], o));
        }
    }
    __shared__ float s2[8], smn[8][6], smx[8][6];
    int lane = threadIdx.x & 31, w = threadIdx.x >> 5;
    if (lane == 0) {
        s2[w] = mn2;
        #pragma unroll
        for (int k = 0; k < 6; ++k) { smn[w][k] = dmn[k]; smx[w][k] = dmx[k]; }
    }
    __syncthreads();
    if (threadIdx.x == 0) {
        float a2 = s2[0];
        float amn[6], amx[6];
        #pragma unroll
        for (int k = 0; k < 6; ++k) { amn[k] = smn[0][k]; amx[k] = smx[0][k]; }
        for (int wi = 1; wi < 8; ++wi) {
            a2 = fmaxf(a2, s2[wi]);
            #pragma unroll
            for (int k = 0; k < 6; ++k) {
                amn[k] = fminf(amn[k], smn[wi][k]);
                amx[k] = fmaxf(amx[k], smx[wi][k]);
            }
        }
        atomicMaxF(&d_maxnorm2, a2);
        #pragma unroll
        for (int k = 0; k < 6; ++k) { atomicMinF(&d_dmin[k], amn[k]); atomicMaxF(&d_dmax[k], amx[k]); }
    }
}

// -------- kernel 2: build U/V + accumulate stage-0 moments (pot = 0) --------
__global__ void k_build(const float* __restrict__ x, const float* __restrict__ y) {
    int p = blockIdx.x * blockDim.x + threadIdx.x;   // exactly 32768 threads
    float s = 1.f / (sqrtf(d_maxnorm2) + 1e-6f);
    float inv_e1 = 1.f / diameter2();

    int q = (p < NPTS) ? p : p - NPTS;
    const float* src = (p < NPTS) ? (x + (size_t)q*6) : (y + (size_t)q*6);
    float* dst = (p < NPTS) ? (d_U + (size_t)q*8) : (d_V + (size_t)q*8);
    float u[6];
    u[0] = src[0]*s; u[1] = src[1]*s; u[2] = src[2]*s;
    u[3] = 0.1f * fminf(fmaxf(src[3], 0.f), 1.f);
    u[4] = 0.1f * fminf(fmaxf(src[4], 0.f), 1.f);
    u[5] = 0.1f * fminf(fmaxf(src[5], 0.f), 1.f);
    float sq = u[0]*u[0]+u[1]*u[1]+u[2]*u[2]+u[3]*u[3]+u[4]*u[4]+u[5]*u[5];
    reinterpret_cast<float4*>(dst)[0] = make_float4(u[0], u[1], u[2], u[3]);
    reinterpret_cast<float4*>(dst)[1] = make_float4(u[4], u[5], sq, 0.f);

    // stage-0 column moments: x-point feeds dir1 (seg 4+b), y-point dir0 (seg b)
    int b = q >> 12;
    int seg = ((p < NPTS) ? 4 : 0) + b;
    float om = ex2(LOG2E * ((0.f - sq) * inv_e1 + BLOG));
    float acc[28];
    acc[0] = om;
    float w[6];
    #pragma unroll
    for (int k = 0; k < 6; ++k) { w[k] = 2.f * u[k] * inv_e1; acc[1+k] = om * w[k]; }
    int cnt = 7;
    #pragma unroll
    for (int k = 0; k < 6; ++k)
        #pragma unroll
        for (int l = k; l < 6; ++l) acc[cnt++] = acc[1+k] * w[l];
    reduce28_atomic(acc, d_M0 + seg*32);
}

// -------- poly eval: S = m0 + u.m1 + 0.5 u'M2 u --------
__device__ __forceinline__ float eval_poly(const float* __restrict__ M, const float* u) {
    float m[28];
    #pragma unroll
    for (int c = 0; c < 28; ++c) m[c] = M[c];
    float S = m[0];
    int cnt = 7;
    #pragma unroll
    for (int k = 0; k < 6; ++k) {
        float inner = m[1+k];                 // m1_k
        inner = fmaf(0.5f * m[cnt], u[k], inner);  // diag
        cnt++;
        #pragma unroll
        for (int l = k+1; l < 6; ++l) { inner = fmaf(m[cnt], u[l], inner); cnt++; }
        S = fmaf(u[k], inner, S);
    }
    return S;
}

// -------- kernel 3: stage-0 row eval + stage-1 moments --------
__global__ void k_poly0() {
    int p = blockIdx.x * blockDim.x + threadIdx.x;
    int q = (p < NPTS) ? p : p - NPTS;
    int dir = (p < NPTS) ? 0 : 1;            // x rows -> f, y rows -> g
    int b = q >> 12;
    const float* Rows = (dir ? d_V : d_U) + (size_t)q*8;
    float u[6], sq;
    {
        float4 a = reinterpret_cast<const float4*>(Rows)[0];
        float4 bb = reinterpret_cast<const float4*>(Rows)[1];
        u[0]=a.x; u[1]=a.y; u[2]=a.z; u[3]=a.w; u[4]=bb.x; u[5]=bb.y; sq=bb.z;
    }
    float eps1 = diameter2();
    float inv_e1 = 1.f / eps1;
    int rowseg = dir*4 + b;
    float S = eval_poly(d_M0 + rowseg*32, u);
    float lnS = logf(S);
    float val = sq - eps1 * lnS;             // f0 / g0
    if (dir == 0) d_f[0][q] = val; else d_g[0][q] = val;

    // stage-1 column moments: weight w' = exp(blog)/S  (since (val-sq)/eps1 = -lnS)
    float om = __fdividef(EBLOG, S);
    int colseg = (dir^1)*4 + b;
    float acc[28];
    acc[0] = om;
    float w[6];
    #pragma unroll
    for (int k = 0; k < 6; ++k) { w[k] = 2.f * u[k] * inv_e1; acc[1+k] = om * w[k]; }
    int cnt = 7;
    #pragma unroll
    for (int k = 0; k < 6; ++k)
        #pragma unroll
        for (int l = k; l < 6; ++l) acc[cnt++] = acc[1+k] * w[l];
    reduce28_atomic(acc, d_M1 + colseg*32);
}

// -------- pack helper for eps2 column data (duplicated pairs, 64B/j) --------
__device__ __forceinline__ void write_pack(float* dst, const float* u, float cw, float h2) {
    reinterpret_cast<float4*>(dst)[0] = make_float4(u[0]*cw, u[0]*cw, u[1]*cw, u[1]*cw);
    reinterpret_cast<float4*>(dst)[1] = make_float4(u[2]*cw, u[2]*cw, u[3]*cw, u[3]*cw);
    reinterpret_cast<float4*>(dst)[2] = make_float4(u[4]*cw, u[4]*cw, u[5]*cw, u[5]*cw);
    reinterpret_cast<float4*>(dst)[3] = make_float4(h2, h2, 0.f, 0.f);
}

// -------- kernel 4: stage-1 row eval + pack eps2 columns for stage 2 --------
__global__ void k_poly1() {
    int p = blockIdx.x * blockDim.x + threadIdx.x;
    int q = (p < NPTS) ? p : p - NPTS;
    int dir = (p < NPTS) ? 0 : 1;
    int b = q >> 12;
    const float* Rows = (dir ? d_V : d_U) + (size_t)q*8;
    float u[6], sq;
    {
        float4 a = reinterpret_cast<const float4*>(Rows)[0];
        float4 bb = reinterpret_cast<const float4*>(Rows)[1];
        u[0]=a.x; u[1]=a.y; u[2]=a.z; u[3]=a.w; u[4]=bb.x; u[5]=bb.y; sq=bb.z;
    }
    float eps1 = diameter2();
    int rowseg = dir*4 + b;
    float S = eval_poly(d_M1 + rowseg*32, u);
    float val = sq - eps1 * logf(S);
    float prev = (dir == 0) ? d_f[0][q] : d_g[0][q];
    float res = 0.5f * (prev + val);         // f1 / g1
    if (dir == 0) d_f[1][q] = res; else d_g[1][q] = res;

    // pack eps2 columns for stage 2 (opposite direction), into Pbuf[0]
    int colseg = (dir^1)*4 + b;
    float cw = 2.f * LOG2E / EPS2;
    float h2 = LOG2E * BLOG + (res - sq) * (LOG2E / EPS2);
    write_pack(d_Pbuf + ((size_t)colseg*NN + (q & (NN-1)))*16, u, cw, h2);
}

// -------- eps2 main: fused both-direction softmin (validated R2 loop) --------
template<bool HASNEXT>
__global__ void __launch_bounds__(256) k_main(int cur, int pp, float alpha, float beta) {
    const int bd = blockIdx.y;
    const int b = bd & 3;
    const int dir = bd >> 2;
    const float* Rows = (dir ? d_V : d_U) + (size_t)b*NN*8;
    const float* fin  = (dir ? d_g[cur] : d_f[cur]) + (size_t)b*NN;
    float* fout       = (dir ? d_g[cur^1] : d_f[cur^1]) + (size_t)b*NN;
    const float* Pin  = d_Pbuf + (size_t)pp*PBUF + (size_t)(dir*4 + b)*NN*16;

    const int lane = threadIdx.x & 31;
    const int warp = threadIdx.x >> 5;
    const int rowbase = blockIdx.x * 128;

    unsigned long long up[2][6];
    #pragma unroll
    for (int pr = 0; pr < 2; ++pr) {
        const float4* ra = reinterpret_cast<const float4*>(Rows + (size_t)(rowbase + lane + 64*pr)*8);
        const float4* rb = reinterpret_cast<const float4*>(Rows + (size_t)(rowbase + lane + 64*pr + 32)*8);
        float4 a0 = ra[0], a1 = ra[1];
        float4 b0 = rb[0], b1 = rb[1];
        up[pr][0] = pack2(a0.x, b0.x); up[pr][1] = pack2(a0.y, b0.y);
        up[pr][2] = pack2(a0.z, b0.z); up[pr][3] = pack2(a0.w, b0.w);
        up[pr][4] = pack2(a1.x, b1.x); up[pr][5] = pack2(a1.y, b1.y);
    }

    const unsigned long long* P8 = reinterpret_cast<const unsigned long long*>(Pin) + (size_t)warp*512*8;

    float m0 = NEG_INF, m1 = NEG_INF, m2 = NEG_INF, m3 = NEG_INF;
    float s0 = 0.f, s1 = 0.f, s2 = 0.f, s3 = 0.f;

    #pragma unroll 4
    for (int j = 0; j < 512; ++j) {
        ulonglong2 q0 = *reinterpret_cast<const ulonglong2*>(P8 + 8*j + 0);
        ulonglong2 q1 = *reinterpret_cast<const ulonglong2*>(P8 + 8*j + 2);
        ulonglong2 q2 = *reinterpret_cast<const ulonglong2*>(P8 + 8*j + 4);
        unsigned long long hp = P8[8*j + 6];
        unsigned long long A0 = hp, A1 = hp;
        FMA2(A0, up[0][0], q0.x, A0);  FMA2(A1, up[1][0], q0.x, A1);
        FMA2(A0, up[0][1], q0.y, A0);  FMA2(A1, up[1][1], q0.y, A1);
        FMA2(A0, up[0][2], q1.x, A0);  FMA2(A1, up[1][2], q1.x, A1);
        FMA2(A0, up[0][3], q1.y, A0);  FMA2(A1, up[1][3], q1.y, A1);
        FMA2(A0, up[0][4], q2.x, A0);  FMA2(A1, up[1][4], q2.x, A1);
        FMA2(A0, up[0][5], q2.y, A0);  FMA2(A1, up[1][5], q2.y, A1);
        float a0, a1, a2, a3;
        unpack2(a0, a1, A0); unpack2(a2, a3, A1);
        { float d = a0 - m0; float ee = ex2(-fabsf(d)); bool up_ = d > 0.f;
          s0 = up_ ? fmaf(s0, ee, 1.f) : (s0 + ee); m0 = fmaxf(m0, a0); }
        { float d = a1 - m1; float ee = ex2(-fabsf(d)); bool up_ = d > 0.f;
          s1 = up_ ? fmaf(s1, ee, 1.f) : (s1 + ee); m1 = fmaxf(m1, a1); }
        { float d = a2 - m2; float ee = ex2(-fabsf(d)); bool up_ = d > 0.f;
          s2 = up_ ? fmaf(s2, ee, 1.f) : (s2 + ee); m2 = fmaxf(m2, a2); }
        { float d = a3 - m3; float ee = ex2(-fabsf(d)); bool up_ = d > 0.f;
          s3 = up_ ? fmaf(s3, ee, 1.f) : (s3 + ee); m3 = fmaxf(m3, a3); }
    }

    __shared__ float shA[8][128];
    __shared__ float shB[8][128];
    shA[warp][lane      ] = m0;  shB[warp][lane      ] = s0;
    shA[warp][lane + 32 ] = m1;  shB[warp][lane + 32 ] = s1;
    shA[warp][lane + 64 ] = m2;  shB[warp][lane + 64 ] = s2;
    shA[warp][lane + 96 ] = m3;  shB[warp][lane + 96 ] = s3;
    __syncthreads();

    if (threadIdx.x < 128) {
        const int t = threadIdx.x;
        const int r = rowbase + t;
        float M = shA[0][t];
        #pragma unroll
        for (int w = 1; w < 8; ++w) M = fmaxf(M, shA[w][t]);
        float S = 0.f;
        #pragma unroll
        for (int w = 0; w < 8; ++w) S += shB[w][t] * exp2f(shA[w][t] - M);
        const float* src = Rows + (size_t)r*8;
        float sq = src[6];
        float val = sq - EPS2 * LN2F * (M + log2f(S));
        float res = beta * val;
        if (alpha != 0.f) res = fmaf(alpha, fin[r], res);
        fout[r] = res;

        if (HASNEXT) {
            float u[6];
            u[0]=src[0]; u[1]=src[1]; u[2]=src[2]; u[3]=src[3]; u[4]=src[4]; u[5]=src[5];
            float cw = 2.f * LOG2E / EPS2;
            float h2 = LOG2E * BLOG + (res - sq) * (LOG2E / EPS2);
            float* dst = d_Pbuf + (size_t)(pp^1)*PBUF + ((size_t)((dir^1)*4 + b)*NN + r)*16;
            write_pack(dst, u, cw, h2);
        }
    }
}

// -------- final mean reduction --------
__global__ void k_out(float* __restrict__ out) {
    float sum = 0.f;
    for (int i = threadIdx.x; i < NPTS; i += 256)
        sum += d_f[1][i] + d_g[1][i];
    #pragma unroll
    for (int o = 16; o; o >>= 1) sum += __shfl_xor_sync(0xffffffffu, sum, o);
    __shared__ float sw[8];
    int lane = threadIdx.x & 31, w = threadIdx.x >> 5;
    if (lane == 0) sw[w] = sum;
    __syncthreads();
    if (threadIdx.x == 0) {
        float t = 0.f;
        #pragma unroll
        for (int wi = 0; wi < 8; ++wi) t += sw[wi];
        out[0] = t * (10.f / (float)NPTS);
    }
}

extern "C" void kernel_launch(void* const* d_in, const int* in_sizes, int n_in,
                              void* d_out, int out_size) {
    (void)in_sizes; (void)n_in; (void)out_size;
    const float* x = (const float*)d_in[0];
    const float* y = (const float*)d_in[1];
    float* out = (float*)d_out;

    k_init<<<1, 256>>>();                              // 0
    k_reduce<<<64, 256>>>(x, y);                       // 1
    k_build<<<128, 256>>>(x, y);                       // 2  (+stage0 moments)
    k_poly0<<<128, 256>>>();                           // 3  f0,g0 (+stage1 moments)
    k_poly1<<<128, 256>>>();                           // 4  f1,g1 (+eps2 pack -> Pbuf[0])

    dim3 g(NN/128, 2*BB);
    // stage 2 (eps2): f2 = 0.5*(f1 + softmin), pack stage-3 columns -> Pbuf[1]
    k_main<true ><<<g, 256>>>(1, 0, 0.5f, 0.5f);       // 5
    // stage 3 (eps2): f_new = softmin only
    k_main<false><<<g, 256>>>(0, 1, 0.0f, 1.0f);       // 6

    k_out<<<1, 256>>>(out);                            // 7
}

// round 4
// speedup vs baseline: 2.6441x; 1.2535x over previous
#include <cuda_runtime.h>
#include <cstdint>

// Fixed shapes: x,y float32 (4,4096,6)
#define BB 4
#define NN 4096
#define NPTS (BB*NN)
#define NBLK 128                      // k_pre grid (co-resident for grid barrier)
#define LOG2E 1.4426950408889634f
#define LN2F  0.6931471805599453f
#define EPS2  1e-4f
#define BLOG  (-8.317766166719343f)   // -log(4096)
#define EBLOG (2.44140625e-4f)        // exp(BLOG)
#define POS_INF (__int_as_float(0x7f800000))
#define NEG_INF (__int_as_float(0xff800000))
#define PBUF (8*NN*16)

// ---- f32x2 packed-math helpers ----
#define FMA2(d,a,b,c) asm("fma.rn.f32x2 %0, %1, %2, %3;" : "=l"(d) : "l"(a), "l"(b), "l"(c))
__device__ __forceinline__ unsigned long long pack2(float lo, float hi) {
    unsigned long long d;
    asm("mov.b64 %0, {%1, %2};" : "=l"(d) : "r"(__float_as_uint(lo)), "r"(__float_as_uint(hi)));
    return d;
}
__device__ __forceinline__ void unpack2(float& lo, float& hi, unsigned long long d) {
    unsigned int a, b;
    asm("mov.b64 {%0, %1}, %2;" : "=r"(a), "=r"(b) : "l"(d));
    lo = __uint_as_float(a); hi = __uint_as_float(b);
}
__device__ __forceinline__ float ex2(float x) {
    float r; asm("ex2.approx.ftz.f32 %0, %1;" : "=f"(r) : "f"(x)); return r;
}
__device__ __forceinline__ float lg2(float x) {
    float r; asm("lg2.approx.ftz.f32 %0, %1;" : "=f"(r) : "f"(x)); return r;
}

// -------- device scratch --------
__device__ __align__(16) float d_U[NPTS*8];
__device__ __align__(16) float d_V[NPTS*8];
__device__ __align__(16) float d_Pbuf[2*PBUF];
__device__ float d_f[2][NPTS];
__device__ float d_g[2][NPTS];
__device__ float d_M0[8*32];
__device__ float d_M1[8*32];
__device__ float d_red[NBLK][16];          // per-block reduction partials
__device__ __align__(16) float2 d_part[32768*4];  // per-(row,chunk) (m,s)
__device__ unsigned d_gen[4];              // grid-barrier generations (monotonic)
__device__ unsigned d_cnt[4];

// -------- software grid barrier (NBLK blocks, all co-resident) --------
__device__ __forceinline__ void grid_barrier(int k) {
    __syncthreads();
    if (threadIdx.x == 0) {
        __threadfence();
        unsigned g = d_gen[k];
        unsigned t = atomicAdd(&d_cnt[k], 1);
        if (t == NBLK - 1) {
            d_cnt[k] = 0;
            __threadfence();
            atomicExch(&d_gen[k], g + 1);
        } else {
            while (*((volatile unsigned*)&d_gen[k]) == g) { }
        }
        __threadfence();
    }
    __syncthreads();
}

// warp-reduce 28 accumulators, then one atomicAdd per lane
__device__ __forceinline__ void reduce28_atomic(const float* acc, float* gdst) {
    int lane = threadIdx.x & 31;
    float mine = 0.f;
    #pragma unroll
    for (int c = 0; c < 28; ++c) {
        float v = acc[c];
        #pragma unroll
        for (int o = 16; o; o >>= 1) v += __shfl_xor_sync(0xffffffffu, v, o);
        if (lane == c) mine = v;
    }
    if (lane < 28) atomicAdd(gdst + lane, mine);
}

__device__ __forceinline__ float eval_poly(const float* __restrict__ M, const float* u) {
    float m[28];
    #pragma unroll
    for (int c = 0; c < 28; ++c) m[c] = M[c];
    float S = m[0];
    int cnt = 7;
    #pragma unroll
    for (int k = 0; k < 6; ++k) {
        float inner = m[1+k];
        inner = fmaf(0.5f * m[cnt], u[k], inner);
        cnt++;
        #pragma unroll
        for (int l = k+1; l < 6; ++l) { inner = fmaf(m[cnt], u[l], inner); cnt++; }
        S = fmaf(u[k], inner, S);
    }
    return S;
}

__device__ __forceinline__ void write_pack(float* dst, const float* u, float cw, float h2) {
    reinterpret_cast<float4*>(dst)[0] = make_float4(u[0]*cw, u[0]*cw, u[1]*cw, u[1]*cw);
    reinterpret_cast<float4*>(dst)[1] = make_float4(u[2]*cw, u[2]*cw, u[3]*cw, u[3]*cw);
    reinterpret_cast<float4*>(dst)[2] = make_float4(u[4]*cw, u[4]*cw, u[5]*cw, u[5]*cw);
    reinterpret_cast<float4*>(dst)[3] = make_float4(h2, h2, 0.f, 0.f);
}

// ============ k_pre: reduce -> build+moments0 -> poly0(+M1) -> poly1(+pack) ============
// grid = NBLK(128) x 256 threads; one point per thread (32768 total).
__global__ void __launch_bounds__(256) k_pre(const float* __restrict__ x,
                                             const float* __restrict__ y) {
    const int tid = threadIdx.x;
    const int p = blockIdx.x * 256 + tid;            // global point id, 0..32767
    const int lane = tid & 31, warp = tid >> 5;
    const int q = (p < NPTS) ? p : p - NPTS;
    const bool isx = (p < NPTS);
    const int b = q >> 12;

    // ---------- Phase R: block-local reduction of 13 stats ----------
    float rv[13];
    {
        const float* src = isx ? (x + (size_t)q*6) : (y + (size_t)q*6);
        float c[6];
        #pragma unroll
        for (int k = 0; k < 6; ++k) c[k] = src[k];
        rv[0] = c[0]*c[0] + c[1]*c[1] + c[2]*c[2];           // max
        #pragma unroll
        for (int k = 0; k < 6; ++k) { rv[1+k] = c[k]; rv[7+k] = c[k]; }  // min / max
    }
    #pragma unroll
    for (int o = 16; o; o >>= 1) {
        rv[0] = fmaxf(rv[0], __shfl_xor_sync(0xffffffffu, rv[0], o));
        #pragma unroll
        for (int k = 1; k <= 6; ++k) rv[k] = fminf(rv[k], __shfl_xor_sync(0xffffffffu, rv[k], o));
        #pragma unroll
        for (int k = 7; k <= 12; ++k) rv[k] = fmaxf(rv[k], __shfl_xor_sync(0xffffffffu, rv[k], o));
    }
    __shared__ float swr[8][13];
    if (lane == 0) {
        #pragma unroll
        for (int k = 0; k < 13; ++k) swr[warp][k] = rv[k];
    }
    // zero moment arrays while waiting (block 0 only)
    if (blockIdx.x == 0) { d_M0[tid] = 0.f; d_M1[tid] = 0.f; }
    __syncthreads();
    if (tid == 0) {
        float a[13];
        #pragma unroll
        for (int k = 0; k < 13; ++k) a[k] = swr[0][k];
        for (int w = 1; w < 8; ++w) {
            a[0] = fmaxf(a[0], swr[w][0]);
            #pragma unroll
            for (int k = 1; k <= 6; ++k) a[k] = fminf(a[k], swr[w][k]);
            #pragma unroll
            for (int k = 7; k <= 12; ++k) a[k] = fmaxf(a[k], swr[w][k]);
        }
        #pragma unroll
        for (int k = 0; k < 13; ++k) d_red[blockIdx.x][k] = a[k];
    }
    grid_barrier(0);

    // ---------- global reduce of 128 partials (every block, redundant) ----------
    __shared__ float sg[128*13];
    if (tid < 128) {
        #pragma unroll
        for (int k = 0; k < 13; ++k) sg[tid*13 + k] = d_red[tid][k];
    }
    __syncthreads();
    for (int s = 64; s >= 1; s >>= 1) {
        if (tid < s) {
            sg[tid*13+0] = fmaxf(sg[tid*13+0], sg[(tid+s)*13+0]);
            #pragma unroll
            for (int k = 1; k <= 6; ++k) sg[tid*13+k] = fminf(sg[tid*13+k], sg[(tid+s)*13+k]);
            #pragma unroll
            for (int k = 7; k <= 12; ++k) sg[tid*13+k] = fmaxf(sg[tid*13+k], sg[(tid+s)*13+k]);
        }
        __syncthreads();
    }
    const float s_scale = 1.f / (sqrtf(sg[0]) + 1e-6f);
    float eps1;
    {
        float e = 0.f;
        #pragma unroll
        for (int k = 0; k < 6; ++k) { float d = sg[7+k] - sg[1+k]; e += d * d; }
        eps1 = e;
    }
    const float inv_e1 = 1.f / eps1;

    // ---------- Phase B: build U/V + stage-0 moments ----------
    float u[6], sq;
    {
        const float* src = isx ? (x + (size_t)q*6) : (y + (size_t)q*6);
        float* dst = isx ? (d_U + (size_t)q*8) : (d_V + (size_t)q*8);
        u[0] = src[0]*s_scale; u[1] = src[1]*s_scale; u[2] = src[2]*s_scale;
        u[3] = 0.1f * fminf(fmaxf(src[3], 0.f), 1.f);
        u[4] = 0.1f * fminf(fmaxf(src[4], 0.f), 1.f);
        u[5] = 0.1f * fminf(fmaxf(src[5], 0.f), 1.f);
        sq = u[0]*u[0]+u[1]*u[1]+u[2]*u[2]+u[3]*u[3]+u[4]*u[4]+u[5]*u[5];
        reinterpret_cast<float4*>(dst)[0] = make_float4(u[0], u[1], u[2], u[3]);
        reinterpret_cast<float4*>(dst)[1] = make_float4(u[4], u[5], sq, 0.f);
    }
    float w6[6];
    #pragma unroll
    for (int k = 0; k < 6; ++k) w6[k] = 2.f * u[k] * inv_e1;
    {
        int seg0 = (isx ? 4 : 0) + b;         // columns for opposite direction
        float om = ex2(LOG2E * ((0.f - sq) * inv_e1 + BLOG));
        float acc[28];
        acc[0] = om;
        #pragma unroll
        for (int k = 0; k < 6; ++k) acc[1+k] = om * w6[k];
        int cnt = 7;
        #pragma unroll
        for (int k = 0; k < 6; ++k)
            #pragma unroll
            for (int l = k; l < 6; ++l) acc[cnt++] = acc[1+k] * w6[l];
        reduce28_atomic(acc, d_M0 + seg0*32);
    }
    grid_barrier(1);

    // ---------- Phase P0: f0/g0 + stage-1 moments ----------
    const int dir = isx ? 0 : 1;
    {
        int rowseg = dir*4 + b;
        float S = eval_poly(d_M0 + rowseg*32, u);
        float val = sq - eps1 * logf(S);
        if (dir == 0) d_f[0][q] = val; else d_g[0][q] = val;
        float om = __fdividef(EBLOG, S);
        int colseg = (dir^1)*4 + b;
        float acc[28];
        acc[0] = om;
        #pragma unroll
        for (int k = 0; k < 6; ++k) acc[1+k] = om * w6[k];
        int cnt = 7;
        #pragma unroll
        for (int k = 0; k < 6; ++k)
            #pragma unroll
            for (int l = k; l < 6; ++l) acc[cnt++] = acc[1+k] * w6[l];
        reduce28_atomic(acc, d_M1 + colseg*32);
    }
    grid_barrier(2);

    // ---------- Phase P1: f1/g1 + pack eps2 columns -> Pbuf[0] ----------
    {
        int rowseg = dir*4 + b;
        float S = eval_poly(d_M1 + rowseg*32, u);
        float val = sq - eps1 * logf(S);
        float prev = (dir == 0) ? d_f[0][q] : d_g[0][q];
        float res = 0.5f * (prev + val);
        if (dir == 0) d_f[1][q] = res; else d_g[1][q] = res;

        int colseg = (dir^1)*4 + b;
        float cw = 2.f * LOG2E / EPS2;
        float h2 = LOG2E * BLOG + (res - sq) * (LOG2E / EPS2);
        write_pack(d_Pbuf + ((size_t)colseg*NN + (q & (NN-1)))*16, u, cw, h2);
    }
}

// ============ eps2 main: partial softmin over 1/4 of j range ============
// grid = (32 rowtiles, 8 segs, 4 jchunks), block 256 (8 warps).
__global__ void __launch_bounds__(256) k_main(int pp) {
    const int seg = blockIdx.y;
    const int b = seg & 3;
    const int dir = seg >> 2;
    const float* Rows = (dir ? d_V : d_U) + (size_t)b*NN*8;
    const float* Pin  = d_Pbuf + (size_t)pp*PBUF + (size_t)seg*NN*16;

    const int lane = threadIdx.x & 31;
    const int warp = threadIdx.x >> 5;
    const int rowbase = blockIdx.x * 128;

    unsigned long long up[2][6];
    #pragma unroll
    for (int pr = 0; pr < 2; ++pr) {
        const float4* ra = reinterpret_cast<const float4*>(Rows + (size_t)(rowbase + lane + 64*pr)*8);
        const float4* rb = reinterpret_cast<const float4*>(Rows + (size_t)(rowbase + lane + 64*pr + 32)*8);
        float4 a0 = ra[0], a1 = ra[1];
        float4 b0 = rb[0], b1 = rb[1];
        up[pr][0] = pack2(a0.x, b0.x); up[pr][1] = pack2(a0.y, b0.y);
        up[pr][2] = pack2(a0.z, b0.z); up[pr][3] = pack2(a0.w, b0.w);
        up[pr][4] = pack2(a1.x, b1.x); up[pr][5] = pack2(a1.y, b1.y);
    }

    const unsigned long long* P8 = reinterpret_cast<const unsigned long long*>(Pin)
                                   + ((size_t)blockIdx.z*1024 + (size_t)warp*128)*8;

    float m0 = NEG_INF, m1 = NEG_INF, m2 = NEG_INF, m3 = NEG_INF;
    float s0 = 0.f, s1 = 0.f, s2 = 0.f, s3 = 0.f;

    #pragma unroll 4
    for (int j = 0; j < 128; ++j) {
        ulonglong2 q0 = *reinterpret_cast<const ulonglong2*>(P8 + 8*j + 0);
        ulonglong2 q1 = *reinterpret_cast<const ulonglong2*>(P8 + 8*j + 2);
        ulonglong2 q2 = *reinterpret_cast<const ulonglong2*>(P8 + 8*j + 4);
        unsigned long long hp = P8[8*j + 6];
        unsigned long long A0 = hp, A1 = hp;
        FMA2(A0, up[0][0], q0.x, A0);  FMA2(A1, up[1][0], q0.x, A1);
        FMA2(A0, up[0][1], q0.y, A0);  FMA2(A1, up[1][1], q0.y, A1);
        FMA2(A0, up[0][2], q1.x, A0);  FMA2(A1, up[1][2], q1.x, A1);
        FMA2(A0, up[0][3], q1.y, A0);  FMA2(A1, up[1][3], q1.y, A1);
        FMA2(A0, up[0][4], q2.x, A0);  FMA2(A1, up[1][4], q2.x, A1);
        FMA2(A0, up[0][5], q2.y, A0);  FMA2(A1, up[1][5], q2.y, A1);
        float a0, a1, a2, a3;
        unpack2(a0, a1, A0); unpack2(a2, a3, A1);
        { float d = a0 - m0; float ee = ex2(-fabsf(d)); bool up_ = d > 0.f;
          s0 = up_ ? fmaf(s0, ee, 1.f) : (s0 + ee); m0 = fmaxf(m0, a0); }
        { float d = a1 - m1; float ee = ex2(-fabsf(d)); bool up_ = d > 0.f;
          s1 = up_ ? fmaf(s1, ee, 1.f) : (s1 + ee); m1 = fmaxf(m1, a1); }
        { float d = a2 - m2; float ee = ex2(-fabsf(d)); bool up_ = d > 0.f;
          s2 = up_ ? fmaf(s2, ee, 1.f) : (s2 + ee); m2 = fmaxf(m2, a2); }
        { float d = a3 - m3; float ee = ex2(-fabsf(d)); bool up_ = d > 0.f;
          s3 = up_ ? fmaf(s3, ee, 1.f) : (s3 + ee); m3 = fmaxf(m3, a3); }
    }

    __shared__ float shA[8][128];
    __shared__ float shB[8][128];
    shA[warp][lane      ] = m0;  shB[warp][lane      ] = s0;
    shA[warp][lane + 32 ] = m1;  shB[warp][lane + 32 ] = s1;
    shA[warp][lane + 64 ] = m2;  shB[warp][lane + 64 ] = s2;
    shA[warp][lane + 96 ] = m3;  shB[warp][lane + 96 ] = s3;
    __syncthreads();

    if (threadIdx.x < 128) {
        const int t = threadIdx.x;
        float M = shA[0][t];
        #pragma unroll
        for (int w = 1; w < 8; ++w) M = fmaxf(M, shA[w][t]);
        float S = 0.f;
        #pragma unroll
        for (int w = 0; w < 8; ++w) S += shB[w][t] * ex2(shA[w][t] - M);
        d_part[((size_t)(seg << 12) + rowbase + t)*4 + blockIdx.z] = make_float2(M, S);
    }
}

// ============ merge partials -> potential update (+ next-stage pack) ============
template<bool HASNEXT>
__global__ void __launch_bounds__(256) k_merge(int cur, int dstpp, float alpha, float beta) {
    const int p = blockIdx.x * 256 + threadIdx.x;    // 0..32767
    const int seg = p >> 12;
    const int r = p & 4095;
    const int dir = seg >> 2;
    const int b = seg & 3;
    const int q = b*NN + r;

    float2 c0 = d_part[(size_t)p*4 + 0];
    float2 c1 = d_part[(size_t)p*4 + 1];
    float2 c2 = d_part[(size_t)p*4 + 2];
    float2 c3 = d_part[(size_t)p*4 + 3];
    float M = fmaxf(fmaxf(c0.x, c1.x), fmaxf(c2.x, c3.x));
    float S = c0.y * ex2(c0.x - M) + c1.y * ex2(c1.x - M)
            + c2.y * ex2(c2.x - M) + c3.y * ex2(c3.x - M);

    const float* src = (dir ? d_V : d_U) + (size_t)q*8;
    float sq = src[6];
    float val = sq - EPS2 * LN2F * (M + lg2(S));
    float fin = (dir ? d_g[cur][q] : d_f[cur][q]);
    float res = beta * val;
    if (alpha != 0.f) res = fmaf(alpha, fin, res);
    if (dir == 0) d_f[cur^1][q] = res; else d_g[cur^1][q] = res;

    if (HASNEXT) {
        float u[6];
        u[0]=src[0]; u[1]=src[1]; u[2]=src[2]; u[3]=src[3]; u[4]=src[4]; u[5]=src[5];
        float cw = 2.f * LOG2E / EPS2;
        float h2 = LOG2E * BLOG + (res - sq) * (LOG2E / EPS2);
        write_pack(d_Pbuf + (size_t)dstpp*PBUF + ((size_t)((dir^1)*4 + b)*NN + r)*16, u, cw, h2);
    }
}

// ============ final mean ============
__global__ void k_out(float* __restrict__ out) {
    float sum = 0.f;
    for (int i = threadIdx.x; i < NPTS; i += 256)
        sum += d_f[1][i] + d_g[1][i];
    #pragma unroll
    for (int o = 16; o; o >>= 1) sum += __shfl_xor_sync(0xffffffffu, sum, o);
    __shared__ float sw[8];
    int lane = threadIdx.x & 31, w = threadIdx.x >> 5;
    if (lane == 0) sw[w] = sum;
    __syncthreads();
    if (threadIdx.x == 0) {
        float t = 0.f;
        #pragma unroll
        for (int wi = 0; wi < 8; ++wi) t += sw[wi];
        out[0] = t * (10.f / (float)NPTS);
    }
}

extern "C" void kernel_launch(void* const* d_in, const int* in_sizes, int n_in,
                              void* d_out, int out_size) {
    (void)in_sizes; (void)n_in; (void)out_size;
    const float* x = (const float*)d_in[0];
    const float* y = (const float*)d_in[1];
    float* out = (float*)d_out;

    dim3 g(32, 8, 4);
    k_pre<<<NBLK, 256>>>(x, y);                       // 1: stats+build+poly0/1+pack(Pbuf0)
    k_main<<<g, 256>>>(0);                            // 2: stage2 partials
    k_merge<true ><<<NBLK, 256>>>(1, 1, 0.5f, 0.5f);  // 3: pot2 -> idx0, pack Pbuf1
    k_main<<<g, 256>>>(1);                            // 4: stage3 partials  (ncu target)
    k_merge<false><<<NBLK, 256>>>(0, 0, 0.0f, 1.0f);  // 5: f_new/g_new -> idx1
    k_out<<<1, 256>>>(out);                           // 6
}